// round 1
// baseline (speedup 1.0000x reference)
#include <cuda_runtime.h>
#include <cstdint>

#define NB 32768
#define ND 512
#define NC 527
#define NPAD 576   // 9 * 64, padded class dim for the GEMM scratch

// Scratch logits (x @ W^T, no bias), fp32. 32768*576*4 = 75.5 MB device global.
__device__ float g_LOG[(size_t)NB * NPAD];

// ---------------------------------------------------------------------------
// K0: zero the two output accumulators (harness poisons d_out with 0xAA)
// ---------------------------------------------------------------------------
__global__ void k_zero(float* out) {
    if (threadIdx.x == 0) { out[0] = 0.0f; out[1] = 0.0f; }
}

// ---------------------------------------------------------------------------
// K1: GEMM  logits[m][n] = sum_k x[m][k] * W[n][k]   (tf32 mma.sync, fp32 acc)
// CTA tile 128x64, BK=16, 8 warps in 4(m) x 2(n), warp tile 32x32.
// ---------------------------------------------------------------------------
#define BM 128
#define BN 64
#define BK 16
#define BKP 20   // padded row stride (floats): bank = 4*r + t pattern, conflict-free frags

__device__ __forceinline__ void mma_tf32(float* c, const float* a, const float* b) {
    asm volatile(
        "mma.sync.aligned.m16n8k8.row.col.f32.tf32.tf32.f32 "
        "{%0,%1,%2,%3}, {%4,%5,%6,%7}, {%8,%9}, {%0,%1,%2,%3};\n"
        : "+f"(c[0]), "+f"(c[1]), "+f"(c[2]), "+f"(c[3])
        : "r"(__float_as_uint(a[0])), "r"(__float_as_uint(a[1])),
          "r"(__float_as_uint(a[2])), "r"(__float_as_uint(a[3])),
          "r"(__float_as_uint(b[0])), "r"(__float_as_uint(b[1])));
}

__global__ __launch_bounds__(256, 2)
void k_gemm(const float* __restrict__ X, const float* __restrict__ W) {
    __shared__ float sA[2][BM * BKP];
    __shared__ float sB[2][BN * BKP];

    const int tid  = threadIdx.x;
    const int lane = tid & 31;
    const int warp = tid >> 5;
    const int wm   = warp & 3;   // warp m index 0..3
    const int wn   = warp >> 2;  // warp n index 0..1
    const int g    = lane >> 2;  // group id 0..7
    const int t    = lane & 3;   // thread-in-group 0..3

    const int row0 = blockIdx.y * BM;
    const int col0 = blockIdx.x * BN;

    // loader mapping: 256 threads; A: 128 rows x 4 float4 (2/thread); B: 64 rows x 4 float4 (1/thread)
    const int lr = tid >> 2;        // 0..63
    const int lc = (tid & 3) * 4;   // 0,4,8,12 (float col of the 16B chunk)

    float acc[2][4][4];
    #pragma unroll
    for (int i = 0; i < 2; i++)
        #pragma unroll
        for (int j = 0; j < 4; j++)
            #pragma unroll
            for (int r = 0; r < 4; r++) acc[i][j][r] = 0.0f;

    auto load_stage = [&](int kt, int buf) {
        const float* Xa = X + (size_t)row0 * ND + kt * BK + lc;
        #pragma unroll
        for (int i = 0; i < 2; i++) {
            int r = lr + 64 * i;
            uint32_t dst = (uint32_t)__cvta_generic_to_shared(&sA[buf][r * BKP + lc]);
            asm volatile("cp.async.cg.shared.global [%0], [%1], 16;\n"
                         :: "r"(dst), "l"(Xa + (size_t)r * ND));
        }
        {
            int gn = col0 + lr;  // global class row of W
            uint32_t dst = (uint32_t)__cvta_generic_to_shared(&sB[buf][lr * BKP + lc]);
            const float* src = W + (size_t)gn * ND + kt * BK + lc;
            int sz = (gn < NC) ? 16 : 0;  // zfill padded classes
            asm volatile("cp.async.cg.shared.global [%0], [%1], 16, %2;\n"
                         :: "r"(dst), "l"(src), "r"(sz));
        }
    };

    auto compute_stage = [&](int buf) {
        #pragma unroll
        for (int ks = 0; ks < 2; ks++) {      // 2 k-steps of 8 per BK=16
            const int k0 = ks * 8;
            float a[2][4], bf[4][2];
            #pragma unroll
            for (int mt = 0; mt < 2; mt++) {
                int r = wm * 32 + mt * 16;
                a[mt][0] = sA[buf][(r + g    ) * BKP + k0 + t];
                a[mt][1] = sA[buf][(r + g + 8) * BKP + k0 + t];
                a[mt][2] = sA[buf][(r + g    ) * BKP + k0 + t + 4];
                a[mt][3] = sA[buf][(r + g + 8) * BKP + k0 + t + 4];
            }
            #pragma unroll
            for (int nt = 0; nt < 4; nt++) {
                int c = wn * 32 + nt * 8 + g;
                bf[nt][0] = sB[buf][c * BKP + k0 + t];
                bf[nt][1] = sB[buf][c * BKP + k0 + t + 4];
            }
            #pragma unroll
            for (int mt = 0; mt < 2; mt++)
                #pragma unroll
                for (int nt = 0; nt < 4; nt++)
                    mma_tf32(acc[mt][nt], a[mt], bf[nt]);
        }
    };

    // software pipeline: 2 stages
    load_stage(0, 0);
    asm volatile("cp.async.commit_group;\n");
    load_stage(1, 1);
    asm volatile("cp.async.commit_group;\n");

    const int NIT = ND / BK;  // 32
    for (int it = 0; it < NIT; it++) {
        asm volatile("cp.async.wait_group 1;\n");
        __syncthreads();
        compute_stage(it & 1);
        __syncthreads();
        if (it + 2 < NIT) load_stage(it + 2, it & 1);
        asm volatile("cp.async.commit_group;\n");
    }

    // epilogue: store fp32 logits to padded scratch
    #pragma unroll
    for (int mt = 0; mt < 2; mt++) {
        int gr = row0 + wm * 32 + mt * 16;
        #pragma unroll
        for (int nt = 0; nt < 4; nt++) {
            int gc = col0 + wn * 32 + nt * 8 + 2 * t;
            float2 v0 = make_float2(acc[mt][nt][0], acc[mt][nt][1]);
            float2 v1 = make_float2(acc[mt][nt][2], acc[mt][nt][3]);
            *(float2*)&g_LOG[(size_t)(gr + g    ) * NPAD + gc] = v0;
            *(float2*)&g_LOG[(size_t)(gr + g + 8) * NPAD + gc] = v1;
        }
    }
}

// ---------------------------------------------------------------------------
// K2: per-row BCE loss + exact top-k hit rate. One warp per row.
// Each lane holds 17 classes (lane + 32*i). Exact k-th largest via 32-bit
// radix select on order-preserving uint keys (matches argsort ranks for
// distinct values). Results accumulated pre-normalized via atomicAdd.
// ---------------------------------------------------------------------------
__global__ __launch_bounds__(256)
void k_reduce(const float* __restrict__ Y, const float* __restrict__ bias,
              const float* __restrict__ pw, float* __restrict__ out) {
    const int warp = threadIdx.x >> 5;
    const int lane = threadIdx.x & 31;
    const int row  = blockIdx.x * 8 + warp;

    const float* lg = g_LOG + (size_t)row * NPAD;
    const float* yr = Y + (size_t)row * NC;

    float    yv[17];
    unsigned u[17];
    int   cnt  = 0;
    float lsum = 0.0f;

    #pragma unroll
    for (int i = 0; i < 17; i++) {
        int c = lane + 32 * i;
        bool v = (c < NC);
        float z = 0.0f, yy = 0.0f;
        if (v) {
            z  = lg[c] + bias[c];
            yy = yr[c];
            float p = pw[c];
            // softplus(z) stable; softplus(-z) = softplus(z) - z (exact identity)
            float sp_pos = fmaxf(z, 0.0f) + log1pf(__expf(-fabsf(z)));
            float sp_neg = sp_pos - z;
            lsum += p * yy * sp_neg + (1.0f - yy) * sp_pos;
            cnt  += (yy != 0.0f);
        }
        yv[i] = v ? yy : 0.0f;
        unsigned bb = __float_as_uint(z);
        unsigned uu = (bb & 0x80000000u) ? ~bb : (bb | 0x80000000u);
        u[i] = v ? uu : 0u;  // 0 = smaller than any valid key
    }

    // k = number of positives in this row (>=1 by construction)
    cnt = __reduce_add_sync(0xffffffffu, cnt);
    #pragma unroll
    for (int o = 16; o; o >>= 1) lsum += __shfl_xor_sync(0xffffffffu, lsum, o);

    // radix select: largest threshold T with count(u >= T) >= k  ==  k-th largest key
    unsigned prefix = 0u;
    for (int bit = 31; bit >= 0; bit--) {
        unsigned cand = prefix | (1u << bit);
        int c2 = 0;
        #pragma unroll
        for (int i = 0; i < 17; i++) c2 += (u[i] >= cand);
        c2 = __reduce_add_sync(0xffffffffu, c2);
        if (c2 >= cnt) prefix = cand;
    }

    int h = 0;
    #pragma unroll
    for (int i = 0; i < 17; i++) h += (yv[i] != 0.0f && u[i] >= prefix) ? 1 : 0;
    h = __reduce_add_sync(0xffffffffu, h);

    if (lane == 0) {
        atomicAdd(&out[0], lsum * (1.0f / ((float)NB * (float)NC)));
        atomicAdd(&out[1], ((float)h / (float)cnt) * (1.0f / (float)NB));
    }
}

// ---------------------------------------------------------------------------
// launch
// ---------------------------------------------------------------------------
extern "C" void kernel_launch(void* const* d_in, const int* in_sizes, int n_in,
                              void* d_out, int out_size) {
    const float *x = nullptr, *y = nullptr, *W = nullptr, *b = nullptr, *pwt = nullptr;
    int n527 = 0;
    for (int i = 0; i < n_in; i++) {
        if      (in_sizes[i] == NB * ND) x = (const float*)d_in[i];
        else if (in_sizes[i] == NB * NC) y = (const float*)d_in[i];
        else if (in_sizes[i] == NC * ND) W = (const float*)d_in[i];
        else if (in_sizes[i] == NC) {
            if (n527 == 0) b = (const float*)d_in[i];
            else           pwt = (const float*)d_in[i];
            n527++;
        }
    }
    float* out = (float*)d_out;

    k_zero<<<1, 32>>>(out);
    dim3 gg(NPAD / BN, NB / BM);  // (9, 256)
    k_gemm<<<gg, 256>>>(x, W);
    k_reduce<<<NB / 8, 256>>>(y, b, pwt, out);
}

// round 3
// speedup vs baseline: 1.0489x; 1.0489x over previous
#include <cuda_runtime.h>
#include <cstdint>

#define NB 32768
#define ND 512
#define NC 527
#define NPAD 576     // 3 * 192

#define BM 128
#define BN 192
#define BK 16
#define BKP 20       // padded row stride in floats (conflict-free fragment loads)
#define STAGES 4
#define NIT (ND / BK)   // 32

#define A_STAGE_FLOATS (BM * BKP)     // 2560
#define B_STAGE_FLOATS (BN * BKP)     // 3840
#define STAGE_FLOATS   (A_STAGE_FLOATS + B_STAGE_FLOATS)
#define SMEM_DYN (STAGES * STAGE_FLOATS * 4)   // 102,400 B

// Scratch logits (x @ W^T + b), fp32. 32768*576*4 = 75.5 MB.
__device__ float g_LOG[(size_t)NB * NPAD];

__device__ __forceinline__ void mma_tf32(float* c, const float* a, const float* b) {
    asm volatile(
        "mma.sync.aligned.m16n8k8.row.col.f32.tf32.tf32.f32 "
        "{%0,%1,%2,%3}, {%4,%5,%6,%7}, {%8,%9}, {%0,%1,%2,%3};\n"
        : "+f"(c[0]), "+f"(c[1]), "+f"(c[2]), "+f"(c[3])
        : "r"(__float_as_uint(a[0])), "r"(__float_as_uint(a[1])),
          "r"(__float_as_uint(a[2])), "r"(__float_as_uint(a[3])),
          "r"(__float_as_uint(b[0])), "r"(__float_as_uint(b[1])));
}

// ---------------------------------------------------------------------------
// K1: tf32 mma.sync GEMM: g_LOG[m][n] = sum_k X[m][k]*W[n][k] + b[n]
// CTA 128x192, 8 warps (2m x 4n), warp tile 64x48, BK=16, 4-stage cp.async.
// Grid (3, 256) x-fastest: the 3 col-tiles of a row-block run in the same
// wave so the A row-block is read from DRAM once and from L2 twice.
// ---------------------------------------------------------------------------
__global__ __launch_bounds__(256, 1)
void k_gemm(const float* __restrict__ X, const float* __restrict__ W,
            const float* __restrict__ bias, float* __restrict__ out) {
    extern __shared__ float sm[];   // [STAGES][A | B]
    __shared__ float sBias[BN];

    const int tid  = threadIdx.x;
    const int lane = tid & 31;
    const int warp = tid >> 5;
    const int wm   = warp & 1;      // 0..1
    const int wn   = warp >> 1;     // 0..3
    const int g    = lane >> 2;     // 0..7
    const int t    = lane & 3;      // 0..3

    const int col0 = blockIdx.x * BN;
    const int row0 = blockIdx.y * BM;

    // fold output zeroing into the first CTA (reduce kernel runs after)
    if (blockIdx.x == 0 && blockIdx.y == 0 && tid < 2) out[tid] = 0.0f;

    for (int i = tid; i < BN; i += 256)
        sBias[i] = (col0 + i < NC) ? bias[col0 + i] : 0.0f;

    float acc[4][6][4];
    #pragma unroll
    for (int i = 0; i < 4; i++)
        #pragma unroll
        for (int j = 0; j < 6; j++)
            #pragma unroll
            for (int r = 0; r < 4; r++) acc[i][j][r] = 0.0f;

    auto load_stage = [&](int kt, int buf) {
        float* sA = sm + buf * STAGE_FLOATS;
        float* sB = sA + A_STAGE_FLOATS;
        const float* Xb = X + (size_t)row0 * ND + kt * BK;
        #pragma unroll
        for (int i = 0; i < 2; i++) {              // A: 512 chunks / 256 thr
            int id = i * 256 + tid;
            int r = id >> 2, c = (id & 3) * 4;
            uint32_t dst = (uint32_t)__cvta_generic_to_shared(&sA[r * BKP + c]);
            asm volatile("cp.async.cg.shared.global [%0], [%1], 16;\n"
                         :: "r"(dst), "l"(Xb + (size_t)r * ND + c));
        }
        #pragma unroll
        for (int i = 0; i < 3; i++) {              // B: 768 chunks / 256 thr
            int id = i * 256 + tid;
            int r = id >> 2, c = (id & 3) * 4;
            int gn = col0 + r;
            uint32_t dst = (uint32_t)__cvta_generic_to_shared(&sB[r * BKP + c]);
            const float* src = W + (size_t)gn * ND + kt * BK + c;
            int sz = (gn < NC) ? 16 : 0;           // zfill padded classes
            asm volatile("cp.async.cg.shared.global [%0], [%1], 16, %2;\n"
                         :: "r"(dst), "l"(src), "r"(sz));
        }
    };

    auto compute_stage = [&](int buf) {
        const float* sA = sm + buf * STAGE_FLOATS;
        const float* sB = sA + A_STAGE_FLOATS;
        #pragma unroll
        for (int ks = 0; ks < 2; ks++) {
            const int k0 = ks * 8;
            float a[4][4], bf[6][2];
            #pragma unroll
            for (int mt = 0; mt < 4; mt++) {
                int r = wm * 64 + mt * 16;
                a[mt][0] = sA[(r + g    ) * BKP + k0 + t];
                a[mt][1] = sA[(r + g + 8) * BKP + k0 + t];
                a[mt][2] = sA[(r + g    ) * BKP + k0 + t + 4];
                a[mt][3] = sA[(r + g + 8) * BKP + k0 + t + 4];
            }
            #pragma unroll
            for (int nt = 0; nt < 6; nt++) {
                int c = wn * 48 + nt * 8 + g;
                bf[nt][0] = sB[c * BKP + k0 + t];
                bf[nt][1] = sB[c * BKP + k0 + t + 4];
            }
            #pragma unroll
            for (int mt = 0; mt < 4; mt++)
                #pragma unroll
                for (int nt = 0; nt < 6; nt++)
                    mma_tf32(acc[mt][nt], a[mt], bf[nt]);
        }
    };

    load_stage(0, 0); asm volatile("cp.async.commit_group;\n");
    load_stage(1, 1); asm volatile("cp.async.commit_group;\n");
    load_stage(2, 2); asm volatile("cp.async.commit_group;\n");

    for (int it = 0; it < NIT; it++) {
        asm volatile("cp.async.wait_group 2;\n");
        __syncthreads();
        compute_stage(it & 3);
        __syncthreads();
        if (it + 3 < NIT) load_stage(it + 3, (it + 3) & 3);
        asm volatile("cp.async.commit_group;\n");
    }

    // epilogue: bias add + store fp32 logits
    #pragma unroll
    for (int mt = 0; mt < 4; mt++) {
        int gr = row0 + wm * 64 + mt * 16 + g;
        #pragma unroll
        for (int nt = 0; nt < 6; nt++) {
            int ci = wn * 48 + nt * 8 + 2 * t;
            float bv0 = sBias[ci], bv1 = sBias[ci + 1];
            int gc = col0 + ci;
            float2 v0 = make_float2(acc[mt][nt][0] + bv0, acc[mt][nt][1] + bv1);
            float2 v1 = make_float2(acc[mt][nt][2] + bv0, acc[mt][nt][3] + bv1);
            *(float2*)&g_LOG[(size_t)(gr    ) * NPAD + gc] = v0;
            *(float2*)&g_LOG[(size_t)(gr + 8) * NPAD + gc] = v1;
        }
    }
}

// ---------------------------------------------------------------------------
// K2: per-row BCE loss + exact top-k hit rate. One warp per row.
// Early-exit radix select on order-preserving uint keys (keys distinct).
// ---------------------------------------------------------------------------
__global__ __launch_bounds__(256)
void k_reduce(const float* __restrict__ Y, const float* __restrict__ pw,
              float* __restrict__ out) {
    const int warp = threadIdx.x >> 5;
    const int lane = threadIdx.x & 31;
    const int row  = blockIdx.x * 8 + warp;

    const float* lg = g_LOG + (size_t)row * NPAD;
    const float* yr = Y + (size_t)row * NC;

    float    yv[17];
    unsigned u[17];
    int   cnt  = 0;
    float lsum = 0.0f;

    #pragma unroll
    for (int i = 0; i < 17; i++) {
        int c = lane + 32 * i;
        bool v = (c < NC);
        float z = 0.0f, yy = 0.0f;
        if (v) {
            z  = lg[c];                  // bias already fused in GEMM
            yy = yr[c];
            float p = pw[c];
            float e  = __expf(-fabsf(z));
            float sp = fmaxf(z, 0.0f) + __logf(1.0f + e);   // softplus(z)
            float w  = 1.0f + yy * (p - 1.0f);
            lsum += w * sp - p * yy * z;
            cnt  += (yy != 0.0f);
        }
        yv[i] = v ? yy : 0.0f;
        unsigned bb = __float_as_uint(z);
        unsigned uu = bb ^ (((unsigned)((int)bb >> 31)) | 0x80000000u);
        u[i] = v ? uu : 0u;              // 0 == below any valid key
    }

    cnt = __reduce_add_sync(0xffffffffu, cnt);
    #pragma unroll
    for (int o = 16; o; o >>= 1) lsum += __shfl_xor_sync(0xffffffffu, lsum, o);

    unsigned prefix = 0u;
    for (int bit = 31; bit >= 0; bit--) {
        unsigned cand = prefix | (1u << bit);
        int c2 = 0;
        #pragma unroll
        for (int i = 0; i < 17; i++) c2 += (u[i] >= cand);
        c2 = __reduce_add_sync(0xffffffffu, c2);
        if (c2 >= cnt) {
            prefix = cand;
            if (c2 == cnt) break;        // selected set is exactly the top-k
        }
    }

    int h = 0;
    #pragma unroll
    for (int i = 0; i < 17; i++) h += (yv[i] != 0.0f && u[i] >= prefix) ? 1 : 0;
    h = __reduce_add_sync(0xffffffffu, h);

    if (lane == 0) {
        atomicAdd(&out[0], lsum * (1.0f / ((float)NB * (float)NC)));
        atomicAdd(&out[1], ((float)h / (float)cnt) * (1.0f / (float)NB));
    }
}

// ---------------------------------------------------------------------------
// launch
// ---------------------------------------------------------------------------
extern "C" void kernel_launch(void* const* d_in, const int* in_sizes, int n_in,
                              void* d_out, int out_size) {
    const float *x = nullptr, *y = nullptr, *W = nullptr, *b = nullptr, *pwt = nullptr;
    int n527 = 0;
    for (int i = 0; i < n_in; i++) {
        if      (in_sizes[i] == NB * ND) x = (const float*)d_in[i];
        else if (in_sizes[i] == NB * NC) y = (const float*)d_in[i];
        else if (in_sizes[i] == NC * ND) W = (const float*)d_in[i];
        else if (in_sizes[i] == NC) {
            if (n527 == 0) b = (const float*)d_in[i];
            else           pwt = (const float*)d_in[i];
            n527++;
        }
    }
    float* out = (float*)d_out;

    static int smem_set = 0;
    if (!smem_set) {
        cudaFuncSetAttribute(k_gemm, cudaFuncAttributeMaxDynamicSharedMemorySize, SMEM_DYN);
        smem_set = 1;
    }

    dim3 gg(NPAD / BN, NB / BM);   // (3, 256), x fastest
    k_gemm<<<gg, 256, SMEM_DYN>>>(x, W, b, out);
    k_reduce<<<NB / 8, 256>>>(y, pwt, out);
}

// round 4
// speedup vs baseline: 1.0513x; 1.0022x over previous
#include <cuda_runtime.h>
#include <cstdint>

#define NB 32768
#define ND 512
#define NC 527
#define NPAD 576     // 3 * 192

#define BM 128
#define BN 192
#define BK 16
#define BKP 20       // padded row stride in floats (conflict-free fragment loads)
#define STAGES 4
#define NIT (ND / BK)   // 32

#define A_STAGE_FLOATS (BM * BKP)     // 2560
#define B_STAGE_FLOATS (BN * BKP)     // 3840
#define STAGE_FLOATS   (A_STAGE_FLOATS + B_STAGE_FLOATS)
#define SMEM_DYN (STAGES * STAGE_FLOATS * 4)   // 102,400 B

// Scratch logits (x @ W^T + b), fp32. 32768*576*4 = 75.5 MB.
__device__ float g_LOG[(size_t)NB * NPAD];

__device__ __forceinline__ void mma_tf32(float* c, const float* a, const float* b) {
    asm volatile(
        "mma.sync.aligned.m16n8k8.row.col.f32.tf32.tf32.f32 "
        "{%0,%1,%2,%3}, {%4,%5,%6,%7}, {%8,%9}, {%0,%1,%2,%3};\n"
        : "+f"(c[0]), "+f"(c[1]), "+f"(c[2]), "+f"(c[3])
        : "r"(__float_as_uint(a[0])), "r"(__float_as_uint(a[1])),
          "r"(__float_as_uint(a[2])), "r"(__float_as_uint(a[3])),
          "r"(__float_as_uint(b[0])), "r"(__float_as_uint(b[1])));
}

// ---------------------------------------------------------------------------
// K1: tf32 mma.sync GEMM: g_LOG[m][n] = sum_k X[m][k]*W[n][k] + b[n]
// CTA 128x192, 8 warps (2m x 4n), warp tile 64x48, BK=16, 4-stage cp.async.
// One __syncthreads per iteration; prefetch issued before compute.
// ---------------------------------------------------------------------------
__global__ __launch_bounds__(256, 1)
void k_gemm(const float* __restrict__ X, const float* __restrict__ W,
            const float* __restrict__ bias, float* __restrict__ out) {
    extern __shared__ float sm[];   // [STAGES][A | B]
    __shared__ float sBias[BN];

    const int tid  = threadIdx.x;
    const int lane = tid & 31;
    const int warp = tid >> 5;
    const int wm   = warp & 1;      // 0..1
    const int wn   = warp >> 1;     // 0..3
    const int g    = lane >> 2;     // 0..7
    const int t    = lane & 3;      // 0..3

    const int col0 = blockIdx.x * BN;
    const int row0 = blockIdx.y * BM;

    // fold output zeroing into the first CTA (reduce kernel runs after)
    if (blockIdx.x == 0 && blockIdx.y == 0 && tid < 2) out[tid] = 0.0f;

    for (int i = tid; i < BN; i += 256)
        sBias[i] = (col0 + i < NC) ? bias[col0 + i] : 0.0f;

    float acc[4][6][4];
    #pragma unroll
    for (int i = 0; i < 4; i++)
        #pragma unroll
        for (int j = 0; j < 6; j++)
            #pragma unroll
            for (int r = 0; r < 4; r++) acc[i][j][r] = 0.0f;

    auto load_stage = [&](int kt, int buf) {
        float* sA = sm + buf * STAGE_FLOATS;
        float* sB = sA + A_STAGE_FLOATS;
        const float* Xb = X + (size_t)row0 * ND + kt * BK;
        #pragma unroll
        for (int i = 0; i < 2; i++) {              // A: 512 chunks / 256 thr
            int id = i * 256 + tid;
            int r = id >> 2, c = (id & 3) * 4;
            uint32_t dst = (uint32_t)__cvta_generic_to_shared(&sA[r * BKP + c]);
            asm volatile("cp.async.cg.shared.global [%0], [%1], 16;\n"
                         :: "r"(dst), "l"(Xb + (size_t)r * ND + c));
        }
        #pragma unroll
        for (int i = 0; i < 3; i++) {              // B: 768 chunks / 256 thr
            int id = i * 256 + tid;
            int r = id >> 2, c = (id & 3) * 4;
            int gn = col0 + r;
            uint32_t dst = (uint32_t)__cvta_generic_to_shared(&sB[r * BKP + c]);
            const float* src = W + (size_t)gn * ND + kt * BK + c;
            int sz = (gn < NC) ? 16 : 0;           // zfill padded classes
            asm volatile("cp.async.cg.shared.global [%0], [%1], 16, %2;\n"
                         :: "r"(dst), "l"(src), "r"(sz));
        }
    };

    auto compute_stage = [&](int buf) {
        const float* sA = sm + buf * STAGE_FLOATS;
        const float* sB = sA + A_STAGE_FLOATS;
        #pragma unroll
        for (int ks = 0; ks < 2; ks++) {
            const int k0 = ks * 8;
            float a[4][4], bf[6][2];
            #pragma unroll
            for (int mt = 0; mt < 4; mt++) {
                int r = wm * 64 + mt * 16;
                a[mt][0] = sA[(r + g    ) * BKP + k0 + t];
                a[mt][1] = sA[(r + g + 8) * BKP + k0 + t];
                a[mt][2] = sA[(r + g    ) * BKP + k0 + t + 4];
                a[mt][3] = sA[(r + g + 8) * BKP + k0 + t + 4];
            }
            #pragma unroll
            for (int nt = 0; nt < 6; nt++) {
                int c = wn * 48 + nt * 8 + g;
                bf[nt][0] = sB[c * BKP + k0 + t];
                bf[nt][1] = sB[c * BKP + k0 + t + 4];
            }
            #pragma unroll
            for (int mt = 0; mt < 4; mt++)
                #pragma unroll
                for (int nt = 0; nt < 6; nt++)
                    mma_tf32(acc[mt][nt], a[mt], bf[nt]);
        }
    };

    load_stage(0, 0); asm volatile("cp.async.commit_group;\n");
    load_stage(1, 1); asm volatile("cp.async.commit_group;\n");
    load_stage(2, 2); asm volatile("cp.async.commit_group;\n");

    for (int it = 0; it < NIT; it++) {
        asm volatile("cp.async.wait_group 2;\n");
        __syncthreads();           // stage it visible; compute(it-1) finished on all threads
        if (it + 3 < NIT) load_stage(it + 3, (it + 3) & 3);   // prefetch first
        asm volatile("cp.async.commit_group;\n");
        compute_stage(it & 3);
    }

    // epilogue: bias add + store fp32 logits
    #pragma unroll
    for (int mt = 0; mt < 4; mt++) {
        int gr = row0 + wm * 64 + mt * 16 + g;
        #pragma unroll
        for (int nt = 0; nt < 6; nt++) {
            int ci = wn * 48 + nt * 8 + 2 * t;
            float bv0 = sBias[ci], bv1 = sBias[ci + 1];
            int gc = col0 + ci;
            float2 v0 = make_float2(acc[mt][nt][0] + bv0, acc[mt][nt][1] + bv1);
            float2 v1 = make_float2(acc[mt][nt][2] + bv0, acc[mt][nt][3] + bv1);
            *(float2*)&g_LOG[(size_t)(gr    ) * NPAD + gc] = v0;
            *(float2*)&g_LOG[(size_t)(gr + 8) * NPAD + gc] = v1;
        }
    }
}

// ---------------------------------------------------------------------------
// K2: per-row BCE loss + exact top-k hit rate. One warp processes FOUR rows
// interleaved (4 independent radix-select chains -> high issue utilization).
// Packed 2x16-bit warp reductions; sticky early break when all rows isolate.
// ---------------------------------------------------------------------------
__global__ __launch_bounds__(256)
void k_reduce(const float* __restrict__ Y, const float* __restrict__ pw,
              float* __restrict__ out) {
    const int warp = threadIdx.x >> 5;
    const int lane = threadIdx.x & 31;
    const int row0 = (blockIdx.x * 8 + warp) * 4;

    unsigned u[4][17];
    unsigned pm[4];
    int      cnt[4];
    float lsum = 0.0f;

    #pragma unroll
    for (int r = 0; r < 4; r++) {
        const float* lg = g_LOG + (size_t)(row0 + r) * NPAD;
        const float* yr = Y + (size_t)(row0 + r) * NC;
        unsigned m = 0;
        #pragma unroll
        for (int i = 0; i < 17; i++) {
            int c = lane + 32 * i;        // max 543 < NPAD: logits always in-bounds
            bool v = (c < NC);
            float z  = lg[c];
            float yy = v ? yr[c] : 0.0f;
            float p  = v ? pw[c] : 0.0f;
            float e  = __expf(-fabsf(z));
            float sp = fmaxf(z, 0.0f) + __logf(1.0f + e);   // softplus(z)
            float w  = 1.0f + yy * (p - 1.0f);
            lsum += v ? (w * sp - p * yy * z) : 0.0f;
            m |= (yy != 0.0f) ? (1u << i) : 0u;
            unsigned bb = __float_as_uint(z);
            unsigned uu = bb ^ (((unsigned)((int)bb >> 31)) | 0x80000000u);
            u[r][i] = v ? uu : 0u;        // 0 sorts below every valid key
        }
        pm[r]  = m;
        cnt[r] = __popc(m);
    }

    {   // per-row positive counts (k), packed 2x16
        int q01 = cnt[0] | (cnt[1] << 16);
        int q23 = cnt[2] | (cnt[3] << 16);
        q01 = __reduce_add_sync(0xffffffffu, q01);
        q23 = __reduce_add_sync(0xffffffffu, q23);
        cnt[0] = q01 & 0xffff; cnt[1] = q01 >> 16;
        cnt[2] = q23 & 0xffff; cnt[3] = q23 >> 16;
    }
    #pragma unroll
    for (int o = 16; o; o >>= 1) lsum += __shfl_xor_sync(0xffffffffu, lsum, o);

    // 4-way interleaved radix select for the k-th largest key of each row
    unsigned pre[4] = {0u, 0u, 0u, 0u};
    int done = 0;
    #pragma unroll 1
    for (int bit = 31; bit >= 0; bit--) {
        const unsigned msk = 1u << bit;
        const unsigned ca0 = pre[0] | msk, ca1 = pre[1] | msk;
        const unsigned ca2 = pre[2] | msk, ca3 = pre[3] | msk;
        int c0 = 0, c1 = 0, c2 = 0, c3 = 0;
        #pragma unroll
        for (int i = 0; i < 17; i++) {
            c0 += (u[0][i] >= ca0);
            c1 += (u[1][i] >= ca1);
            c2 += (u[2][i] >= ca2);
            c3 += (u[3][i] >= ca3);
        }
        int q01 = c0 | (c1 << 16);
        int q23 = c2 | (c3 << 16);
        q01 = __reduce_add_sync(0xffffffffu, q01);
        q23 = __reduce_add_sync(0xffffffffu, q23);
        c0 = q01 & 0xffff; c1 = q01 >> 16;
        c2 = q23 & 0xffff; c3 = q23 >> 16;
        if (c0 >= cnt[0]) pre[0] = ca0;
        if (c1 >= cnt[1]) pre[1] = ca1;
        if (c2 >= cnt[2]) pre[2] = ca2;
        if (c3 >= cnt[3]) pre[3] = ca3;
        done |= (c0 == cnt[0]) | ((c1 == cnt[1]) << 1)
              | ((c2 == cnt[2]) << 2) | ((c3 == cnt[3]) << 3);
        if (done == 15) break;
    }

    // hits: positives at-or-above each row's threshold (packed 4x8-bit redux)
    int h0 = 0, h1 = 0, h2 = 0, h3 = 0;
    #pragma unroll
    for (int i = 0; i < 17; i++) {
        h0 += (((pm[0] >> i) & 1u) && (u[0][i] >= pre[0])) ? 1 : 0;
        h1 += (((pm[1] >> i) & 1u) && (u[1][i] >= pre[1])) ? 1 : 0;
        h2 += (((pm[2] >> i) & 1u) && (u[2][i] >= pre[2])) ? 1 : 0;
        h3 += (((pm[3] >> i) & 1u) && (u[3][i] >= pre[3])) ? 1 : 0;
    }
    int hh = h0 | (h1 << 8) | (h2 << 16) | (h3 << 24);
    hh = __reduce_add_sync(0xffffffffu, hh);

    if (lane == 0) {
        float sc = (float)((hh      ) & 255) / (float)cnt[0]
                 + (float)((hh >> 8 ) & 255) / (float)cnt[1]
                 + (float)((hh >> 16) & 255) / (float)cnt[2]
                 + (float)((hh >> 24) & 255) / (float)cnt[3];
        atomicAdd(&out[0], lsum * (1.0f / ((float)NB * (float)NC)));
        atomicAdd(&out[1], sc * (1.0f / (float)NB));
    }
}

// ---------------------------------------------------------------------------
// launch
// ---------------------------------------------------------------------------
extern "C" void kernel_launch(void* const* d_in, const int* in_sizes, int n_in,
                              void* d_out, int out_size) {
    const float *x = nullptr, *y = nullptr, *W = nullptr, *b = nullptr, *pwt = nullptr;
    int n527 = 0;
    for (int i = 0; i < n_in; i++) {
        if      (in_sizes[i] == NB * ND) x = (const float*)d_in[i];
        else if (in_sizes[i] == NB * NC) y = (const float*)d_in[i];
        else if (in_sizes[i] == NC * ND) W = (const float*)d_in[i];
        else if (in_sizes[i] == NC) {
            if (n527 == 0) b = (const float*)d_in[i];
            else           pwt = (const float*)d_in[i];
            n527++;
        }
    }
    float* out = (float*)d_out;

    static int smem_set = 0;
    if (!smem_set) {
        cudaFuncSetAttribute(k_gemm, cudaFuncAttributeMaxDynamicSharedMemorySize, SMEM_DYN);
        smem_set = 1;
    }

    dim3 gg(NPAD / BN, NB / BM);   // (3, 256), x fastest
    k_gemm<<<gg, 256, SMEM_DYN>>>(x, W, b, out);
    k_reduce<<<NB / 32, 256>>>(y, pwt, out);
}

// round 5
// speedup vs baseline: 1.3908x; 1.3230x over previous
#include <cuda_runtime.h>
#include <cuda_fp16.h>
#include <cstdint>

#define NB 32768
#define ND 512
#define NC 527
#define NPAD 576     // 3 * 192

#define BM 128
#define BN 192
#define BKH 32          // halfs per K-stage
#define RPAD 40         // padded row stride in halfs (80B; conflict-free frag LDS)
#define STAGES 4
#define NIT (ND / BKH)  // 16

#define A_STAGE_H (BM * RPAD)   // 5120 halfs
#define B_STAGE_H (BN * RPAD)   // 7680 halfs
#define STAGE_H   (A_STAGE_H + B_STAGE_H)
#define SMEM_DYN  (STAGES * STAGE_H * 2)   // 102,400 B

// Scratch: fp16 copies of X and (padded) W, fp32 logits.
__device__ __half g_Xh[(size_t)NB * ND];     // 32 MB
__device__ __half g_Wh[(size_t)NPAD * ND];   // 0.56 MB (rows >= NC zeroed)
__device__ float  g_LOG[(size_t)NB * NPAD];  // 75.5 MB

// ---------------------------------------------------------------------------
// K0: fp32 -> fp16 conversion (memory-bound, ~96 MB of traffic)
// ---------------------------------------------------------------------------
__global__ __launch_bounds__(256)
void k_conv(const float* __restrict__ X, const float* __restrict__ W) {
    const size_t stride = (size_t)gridDim.x * blockDim.x;
    size_t i0 = (size_t)blockIdx.x * blockDim.x + threadIdx.x;

    const float4* X4 = (const float4*)X;
    const size_t nx4 = (size_t)NB * ND / 4;
    for (size_t j = i0; j < nx4; j += stride) {
        float4 v = X4[j];
        __half2 h0 = __floats2half2_rn(v.x, v.y);
        __half2 h1 = __floats2half2_rn(v.z, v.w);
        uint2 p;
        p.x = *(uint32_t*)&h0; p.y = *(uint32_t*)&h1;
        *(uint2*)&g_Xh[j * 4] = p;
    }

    const size_t nw4 = (size_t)NPAD * ND / 4;   // 73728 float4-equivalents
    for (size_t j = i0; j < nw4; j += stride) {
        size_t row = j >> 7;            // 128 float4 per 512-col row
        uint2 p = make_uint2(0u, 0u);
        if (row < NC) {
            float4 v = *(const float4*)&W[j * 4];
            __half2 h0 = __floats2half2_rn(v.x, v.y);
            __half2 h1 = __floats2half2_rn(v.z, v.w);
            p.x = *(uint32_t*)&h0; p.y = *(uint32_t*)&h1;
        }
        *(uint2*)&g_Wh[j * 4] = p;
    }
}

__device__ __forceinline__ void mma_f16(float* c, const uint32_t* a, const uint32_t* b) {
    asm volatile(
        "mma.sync.aligned.m16n8k16.row.col.f32.f16.f16.f32 "
        "{%0,%1,%2,%3}, {%4,%5,%6,%7}, {%8,%9}, {%0,%1,%2,%3};\n"
        : "+f"(c[0]), "+f"(c[1]), "+f"(c[2]), "+f"(c[3])
        : "r"(a[0]), "r"(a[1]), "r"(a[2]), "r"(a[3]), "r"(b[0]), "r"(b[1]));
}

// ---------------------------------------------------------------------------
// K1: fp16 mma GEMM: g_LOG[m][n] = sum_k Xh[m][k]*Wh[n][k] + b[n]
// CTA 128x192, 8 warps (2m x 4n), warp tile 64x48, BK=32 halfs, 4-stage ring.
// ---------------------------------------------------------------------------
__global__ __launch_bounds__(256, 1)
void k_gemm(const __half* __restrict__ Xh, const __half* __restrict__ Wh,
            const float* __restrict__ bias, float* __restrict__ out) {
    extern __shared__ __half smh[];   // [STAGES][A | B], RPAD-padded rows
    __shared__ float sBias[BN];

    const int tid  = threadIdx.x;
    const int lane = tid & 31;
    const int warp = tid >> 5;
    const int wm   = warp & 1;      // 0..1
    const int wn   = warp >> 1;     // 0..3
    const int g    = lane >> 2;     // 0..7
    const int t    = lane & 3;      // 0..3

    const int col0 = blockIdx.x * BN;
    const int row0 = blockIdx.y * BM;

    if (blockIdx.x == 0 && blockIdx.y == 0 && tid < 2) out[tid] = 0.0f;

    for (int i = tid; i < BN; i += 256)
        sBias[i] = (col0 + i < NC) ? bias[col0 + i] : 0.0f;

    float acc[4][6][4];
    #pragma unroll
    for (int i = 0; i < 4; i++)
        #pragma unroll
        for (int j = 0; j < 6; j++)
            #pragma unroll
            for (int r = 0; r < 4; r++) acc[i][j][r] = 0.0f;

    auto load_stage = [&](int kt, int buf) {
        __half* sA = smh + buf * STAGE_H;
        __half* sB = sA + A_STAGE_H;
        const __half* Xb = Xh + (size_t)row0 * ND + kt * BKH;
        #pragma unroll
        for (int i = 0; i < 2; i++) {              // A: 512 x 16B chunks / 256 thr
            int id = i * 256 + tid;
            int r = id >> 2, c = (id & 3) * 8;     // 8 halfs per chunk
            uint32_t dst = (uint32_t)__cvta_generic_to_shared(&sA[r * RPAD + c]);
            asm volatile("cp.async.ca.shared.global [%0], [%1], 16;\n"
                         :: "r"(dst), "l"(Xb + (size_t)r * ND + c));
        }
        const __half* Wb = Wh + (size_t)col0 * ND + kt * BKH;
        #pragma unroll
        for (int i = 0; i < 3; i++) {              // B: 768 x 16B chunks / 256 thr
            int id = i * 256 + tid;
            int r = id >> 2, c = (id & 3) * 8;
            uint32_t dst = (uint32_t)__cvta_generic_to_shared(&sB[r * RPAD + c]);
            asm volatile("cp.async.ca.shared.global [%0], [%1], 16;\n"
                         :: "r"(dst), "l"(Wb + (size_t)r * ND + c));
        }
    };

    auto compute_stage = [&](int buf) {
        const __half* sA = smh + buf * STAGE_H;
        const __half* sB = sA + A_STAGE_H;
        #pragma unroll
        for (int ks = 0; ks < 2; ks++) {           // 2 x k16 per BK=32
            const int k0 = ks * 16 + 2 * t;
            uint32_t a[4][4], bf[6][2];
            #pragma unroll
            for (int mt = 0; mt < 4; mt++) {
                int r = wm * 64 + mt * 16 + g;
                a[mt][0] = *(const uint32_t*)&sA[(r    ) * RPAD + k0    ];
                a[mt][1] = *(const uint32_t*)&sA[(r + 8) * RPAD + k0    ];
                a[mt][2] = *(const uint32_t*)&sA[(r    ) * RPAD + k0 + 8];
                a[mt][3] = *(const uint32_t*)&sA[(r + 8) * RPAD + k0 + 8];
            }
            #pragma unroll
            for (int nt = 0; nt < 6; nt++) {
                int c = wn * 48 + nt * 8 + g;
                bf[nt][0] = *(const uint32_t*)&sB[c * RPAD + k0    ];
                bf[nt][1] = *(const uint32_t*)&sB[c * RPAD + k0 + 8];
            }
            #pragma unroll
            for (int mt = 0; mt < 4; mt++)
                #pragma unroll
                for (int nt = 0; nt < 6; nt++)
                    mma_f16(acc[mt][nt], a[mt], bf[nt]);
        }
    };

    load_stage(0, 0); asm volatile("cp.async.commit_group;\n");
    load_stage(1, 1); asm volatile("cp.async.commit_group;\n");
    load_stage(2, 2); asm volatile("cp.async.commit_group;\n");

    for (int it = 0; it < NIT; it++) {
        asm volatile("cp.async.wait_group 2;\n");
        __syncthreads();
        if (it + 3 < NIT) load_stage(it + 3, (it + 3) & 3);   // prefetch first
        asm volatile("cp.async.commit_group;\n");
        compute_stage(it & 3);
    }

    // epilogue: bias add + store fp32 logits
    #pragma unroll
    for (int mt = 0; mt < 4; mt++) {
        int gr = row0 + wm * 64 + mt * 16 + g;
        #pragma unroll
        for (int nt = 0; nt < 6; nt++) {
            int ci = wn * 48 + nt * 8 + 2 * t;
            float bv0 = sBias[ci], bv1 = sBias[ci + 1];
            int gc = col0 + ci;
            float2 v0 = make_float2(acc[mt][nt][0] + bv0, acc[mt][nt][1] + bv1);
            float2 v1 = make_float2(acc[mt][nt][2] + bv0, acc[mt][nt][3] + bv1);
            *(float2*)&g_LOG[(size_t)(gr    ) * NPAD + gc] = v0;
            *(float2*)&g_LOG[(size_t)(gr + 8) * NPAD + gc] = v1;
        }
    }
}

// ---------------------------------------------------------------------------
// K2: per-row BCE loss + exact top-k hit rate. One warp handles TWO rows
// interleaved (ILP on the redux chain without blowing registers).
// ---------------------------------------------------------------------------
__global__ __launch_bounds__(256)
void k_reduce(const float* __restrict__ Y, const float* __restrict__ pw,
              float* __restrict__ out) {
    const int warp = threadIdx.x >> 5;
    const int lane = threadIdx.x & 31;
    const int row0 = (blockIdx.x * 8 + warp) * 2;

    unsigned u[2][17];
    unsigned pm[2];
    int      cnt[2];
    float lsum = 0.0f;

    #pragma unroll
    for (int r = 0; r < 2; r++) {
        const float* lg = g_LOG + (size_t)(row0 + r) * NPAD;
        const float* yr = Y + (size_t)(row0 + r) * NC;
        unsigned m = 0;
        #pragma unroll
        for (int i = 0; i < 17; i++) {
            int c = lane + 32 * i;        // max 543 < NPAD: logits in-bounds
            bool v = (c < NC);
            float z  = lg[c];
            float yy = v ? yr[c] : 0.0f;
            float p  = v ? pw[c] : 0.0f;
            float e  = __expf(-fabsf(z));
            float sp = fmaxf(z, 0.0f) + __logf(1.0f + e);   // softplus(z)
            float w  = 1.0f + yy * (p - 1.0f);
            lsum += v ? (w * sp - p * yy * z) : 0.0f;
            m |= (yy != 0.0f) ? (1u << i) : 0u;
            unsigned bb = __float_as_uint(z);
            unsigned uu = bb ^ (((unsigned)((int)bb >> 31)) | 0x80000000u);
            u[r][i] = v ? uu : 0u;        // 0 sorts below every valid key
        }
        pm[r]  = m;
        cnt[r] = __popc(m);
    }

    {
        int q = cnt[0] | (cnt[1] << 16);
        q = __reduce_add_sync(0xffffffffu, q);
        cnt[0] = q & 0xffff; cnt[1] = q >> 16;
    }
    #pragma unroll
    for (int o = 16; o; o >>= 1) lsum += __shfl_xor_sync(0xffffffffu, lsum, o);

    // 2-way interleaved radix select for the k-th largest key of each row
    unsigned pre[2] = {0u, 0u};
    int done = 0;
    #pragma unroll 1
    for (int bit = 31; bit >= 0; bit--) {
        const unsigned msk = 1u << bit;
        const unsigned ca0 = pre[0] | msk, ca1 = pre[1] | msk;
        int c0 = 0, c1 = 0;
        #pragma unroll
        for (int i = 0; i < 17; i++) {
            c0 += (u[0][i] >= ca0);
            c1 += (u[1][i] >= ca1);
        }
        int q = c0 | (c1 << 16);
        q = __reduce_add_sync(0xffffffffu, q);
        c0 = q & 0xffff; c1 = q >> 16;
        if (c0 >= cnt[0]) pre[0] = ca0;
        if (c1 >= cnt[1]) pre[1] = ca1;
        done |= (c0 == cnt[0]) | ((c1 == cnt[1]) << 1);
        if (done == 3) break;
    }

    int h0 = 0, h1 = 0;
    #pragma unroll
    for (int i = 0; i < 17; i++) {
        h0 += (((pm[0] >> i) & 1u) && (u[0][i] >= pre[0])) ? 1 : 0;
        h1 += (((pm[1] >> i) & 1u) && (u[1][i] >= pre[1])) ? 1 : 0;
    }
    int hh = h0 | (h1 << 16);
    hh = __reduce_add_sync(0xffffffffu, hh);

    if (lane == 0) {
        float sc = (float)(hh & 0xffff) / (float)cnt[0]
                 + (float)(hh >> 16)    / (float)cnt[1];
        atomicAdd(&out[0], lsum * (1.0f / ((float)NB * (float)NC)));
        atomicAdd(&out[1], sc * (1.0f / (float)NB));
    }
}

// ---------------------------------------------------------------------------
// launch
// ---------------------------------------------------------------------------
extern "C" void kernel_launch(void* const* d_in, const int* in_sizes, int n_in,
                              void* d_out, int out_size) {
    const float *x = nullptr, *y = nullptr, *W = nullptr, *b = nullptr, *pwt = nullptr;
    int n527 = 0;
    for (int i = 0; i < n_in; i++) {
        if      (in_sizes[i] == NB * ND) x = (const float*)d_in[i];
        else if (in_sizes[i] == NB * NC) y = (const float*)d_in[i];
        else if (in_sizes[i] == NC * ND) W = (const float*)d_in[i];
        else if (in_sizes[i] == NC) {
            if (n527 == 0) b = (const float*)d_in[i];
            else           pwt = (const float*)d_in[i];
            n527++;
        }
    }
    float* out = (float*)d_out;

    static int smem_set = 0;
    if (!smem_set) {
        cudaFuncSetAttribute(k_gemm, cudaFuncAttributeMaxDynamicSharedMemorySize, SMEM_DYN);
        smem_set = 1;
    }

    __half *xh, *wh;
    cudaGetSymbolAddress((void**)&xh, g_Xh);
    cudaGetSymbolAddress((void**)&wh, g_Wh);

    k_conv<<<2048, 256>>>(x, W);
    dim3 gg(NPAD / BN, NB / BM);   // (3, 256), x fastest
    k_gemm<<<gg, 256, SMEM_DYN>>>(xh, wh, b, out);
    k_reduce<<<NB / 16, 256>>>(y, pwt, out);
}

// round 6
// speedup vs baseline: 1.5191x; 1.0923x over previous
#include <cuda_runtime.h>
#include <cuda_fp16.h>
#include <cstdint>

#define NB 32768
#define ND 512
#define NC 527
#define NPAD 576     // 3 * 192

#define BM 128
#define BN 192
#define BKH 32          // halfs per K-stage
#define RPAD 40         // padded row stride in halfs (80B; conflict-free LDSM)
#define STAGES 4
#define NIT (ND / BKH)  // 16

#define A_STAGE_H (BM * RPAD)   // 5120 halfs
#define B_STAGE_H (BN * RPAD)   // 7680 halfs
#define STAGE_H   (A_STAGE_H + B_STAGE_H)
#define SMEM_DYN  (STAGES * STAGE_H * 2)   // 102,400 B

// Scratch: fp16 copies of X and (padded) W, fp32 logits.
__device__ __half g_Xh[(size_t)NB * ND];     // 32 MB
__device__ __half g_Wh[(size_t)NPAD * ND];   // 0.56 MB (rows >= NC zeroed)
__device__ float  g_LOG[(size_t)NB * NPAD];  // 75.5 MB

// ---------------------------------------------------------------------------
// K0: fp32 -> fp16 conversion
// ---------------------------------------------------------------------------
__global__ __launch_bounds__(256)
void k_conv(const float* __restrict__ X, const float* __restrict__ W) {
    const size_t stride = (size_t)gridDim.x * blockDim.x;
    size_t i0 = (size_t)blockIdx.x * blockDim.x + threadIdx.x;

    const float4* X4 = (const float4*)X;
    const size_t nx4 = (size_t)NB * ND / 4;
    for (size_t j = i0; j < nx4; j += stride) {
        float4 v = X4[j];
        __half2 h0 = __floats2half2_rn(v.x, v.y);
        __half2 h1 = __floats2half2_rn(v.z, v.w);
        uint2 p;
        p.x = *(uint32_t*)&h0; p.y = *(uint32_t*)&h1;
        *(uint2*)&g_Xh[j * 4] = p;
    }

    const size_t nw4 = (size_t)NPAD * ND / 4;
    for (size_t j = i0; j < nw4; j += stride) {
        size_t row = j >> 7;            // 128 float4 per 512-col row
        uint2 p = make_uint2(0u, 0u);
        if (row < NC) {
            float4 v = *(const float4*)&W[j * 4];
            __half2 h0 = __floats2half2_rn(v.x, v.y);
            __half2 h1 = __floats2half2_rn(v.z, v.w);
            p.x = *(uint32_t*)&h0; p.y = *(uint32_t*)&h1;
        }
        *(uint2*)&g_Wh[j * 4] = p;
    }
}

__device__ __forceinline__ void mma_f16(float* c, const uint32_t* a, const uint32_t* b) {
    asm volatile(
        "mma.sync.aligned.m16n8k16.row.col.f32.f16.f16.f32 "
        "{%0,%1,%2,%3}, {%4,%5,%6,%7}, {%8,%9}, {%0,%1,%2,%3};\n"
        : "+f"(c[0]), "+f"(c[1]), "+f"(c[2]), "+f"(c[3])
        : "r"(a[0]), "r"(a[1]), "r"(a[2]), "r"(a[3]), "r"(b[0]), "r"(b[1]));
}

__device__ __forceinline__ void ldsm_x4(uint32_t* r, uint32_t addr) {
    asm volatile("ldmatrix.sync.aligned.m8n8.x4.shared.b16 {%0,%1,%2,%3}, [%4];"
                 : "=r"(r[0]), "=r"(r[1]), "=r"(r[2]), "=r"(r[3]) : "r"(addr));
}

// ---------------------------------------------------------------------------
// K1: fp16 mma GEMM: g_LOG[m][n] = sum_k Xh[m][k]*Wh[n][k] + b[n]
// CTA 128x192, 8 warps (2m x 4n), warp tile 64x48, BK=32 halfs, 4-stage ring.
// Fragments via ldmatrix.x4 (14 LDSM per warp-iter instead of 56 LDS.32).
// ---------------------------------------------------------------------------
__global__ __launch_bounds__(256, 1)
void k_gemm(const __half* __restrict__ Xh, const __half* __restrict__ Wh,
            const float* __restrict__ bias, float* __restrict__ out) {
    extern __shared__ __half smh[];   // [STAGES][A | B], RPAD-padded rows
    __shared__ float sBias[BN];

    const int tid  = threadIdx.x;
    const int lane = tid & 31;
    const int warp = tid >> 5;
    const int wm   = warp & 1;      // 0..1
    const int wn   = warp >> 1;     // 0..3
    const int g    = lane >> 2;     // 0..7
    const int t    = lane & 3;      // 0..3

    const int col0 = blockIdx.x * BN;
    const int row0 = blockIdx.y * BM;

    if (blockIdx.x == 0 && blockIdx.y == 0 && tid < 2) out[tid] = 0.0f;

    for (int i = tid; i < BN; i += 256)
        sBias[i] = (col0 + i < NC) ? bias[col0 + i] : 0.0f;

    // ldmatrix per-lane offsets (in halfs)
    // A x4: rows base+(lane&7)+((lane>>3)&1)*8, col k0+(lane>>4)*8
    const int aRow = (lane & 7) + ((lane >> 3) & 1) * 8;
    const int aCol = (lane >> 4) * 8;
    // B x4 (2 n-tiles): rows n0+(lane&7)+(lane>>4)*8, col k0+((lane>>3)&1)*8
    const int bRow = (lane & 7) + (lane >> 4) * 8;
    const int bCol = ((lane >> 3) & 1) * 8;

    const uint32_t smBase = (uint32_t)__cvta_generic_to_shared(smh);

    float acc[4][6][4];
    #pragma unroll
    for (int i = 0; i < 4; i++)
        #pragma unroll
        for (int j = 0; j < 6; j++)
            #pragma unroll
            for (int r = 0; r < 4; r++) acc[i][j][r] = 0.0f;

    auto load_stage = [&](int kt, int buf) {
        __half* sA = smh + buf * STAGE_H;
        __half* sB = sA + A_STAGE_H;
        const __half* Xb = Xh + (size_t)row0 * ND + kt * BKH;
        #pragma unroll
        for (int i = 0; i < 2; i++) {              // A: 512 x 16B chunks / 256 thr
            int id = i * 256 + tid;
            int r = id >> 2, c = (id & 3) * 8;
            uint32_t dst = (uint32_t)__cvta_generic_to_shared(&sA[r * RPAD + c]);
            asm volatile("cp.async.ca.shared.global [%0], [%1], 16;\n"
                         :: "r"(dst), "l"(Xb + (size_t)r * ND + c));
        }
        const __half* Wb = Wh + (size_t)col0 * ND + kt * BKH;
        #pragma unroll
        for (int i = 0; i < 3; i++) {              // B: 768 x 16B chunks / 256 thr
            int id = i * 256 + tid;
            int r = id >> 2, c = (id & 3) * 8;
            uint32_t dst = (uint32_t)__cvta_generic_to_shared(&sB[r * RPAD + c]);
            asm volatile("cp.async.ca.shared.global [%0], [%1], 16;\n"
                         :: "r"(dst), "l"(Wb + (size_t)r * ND + c));
        }
    };

    auto compute_stage = [&](int buf) {
        const uint32_t sA = smBase + (buf * STAGE_H) * 2;
        const uint32_t sB = sA + A_STAGE_H * 2;
        #pragma unroll
        for (int ks = 0; ks < 2; ks++) {           // 2 x k16 per BK=32
            const int k0 = ks * 16;
            uint32_t a[4][4], bf[3][4];
            #pragma unroll
            for (int mt = 0; mt < 4; mt++) {
                int r = wm * 64 + mt * 16 + aRow;
                ldsm_x4(a[mt], sA + (r * RPAD + k0 + aCol) * 2);
            }
            #pragma unroll
            for (int nb = 0; nb < 3; nb++) {       // 2 n-tiles per LDSM
                int c = wn * 48 + nb * 16 + bRow;
                ldsm_x4(bf[nb], sB + (c * RPAD + k0 + bCol) * 2);
            }
            #pragma unroll
            for (int mt = 0; mt < 4; mt++)
                #pragma unroll
                for (int nt = 0; nt < 6; nt++)
                    mma_f16(acc[mt][nt], a[mt], &bf[nt >> 1][(nt & 1) * 2]);
        }
    };

    load_stage(0, 0); asm volatile("cp.async.commit_group;\n");
    load_stage(1, 1); asm volatile("cp.async.commit_group;\n");
    load_stage(2, 2); asm volatile("cp.async.commit_group;\n");

    for (int it = 0; it < NIT; it++) {
        asm volatile("cp.async.wait_group 2;\n");
        __syncthreads();
        if (it + 3 < NIT) load_stage(it + 3, (it + 3) & 3);   // prefetch first
        asm volatile("cp.async.commit_group;\n");
        compute_stage(it & 3);
    }

    // epilogue: bias add + store fp32 logits
    #pragma unroll
    for (int mt = 0; mt < 4; mt++) {
        int gr = row0 + wm * 64 + mt * 16 + g;
        #pragma unroll
        for (int nt = 0; nt < 6; nt++) {
            int ci = wn * 48 + nt * 8 + 2 * t;
            float bv0 = sBias[ci], bv1 = sBias[ci + 1];
            int gc = col0 + ci;
            float2 v0 = make_float2(acc[mt][nt][0] + bv0, acc[mt][nt][1] + bv1);
            float2 v1 = make_float2(acc[mt][nt][2] + bv0, acc[mt][nt][3] + bv1);
            *(float2*)&g_LOG[(size_t)(gr    ) * NPAD + gc] = v0;
            *(float2*)&g_LOG[(size_t)(gr + 8) * NPAD + gc] = v1;
        }
    }
}

// ---------------------------------------------------------------------------
// K2: per-row BCE loss + exact top-k hit rate. One warp handles TWO rows.
// Radix select processes TWO bits per pass (3 packed candidate counts per
// REDUX, one REDUX per row, pipelined) -> half the serial pass count.
// ---------------------------------------------------------------------------
__global__ __launch_bounds__(256)
void k_reduce(const float* __restrict__ Y, const float* __restrict__ pw,
              float* __restrict__ out) {
    const int warp = threadIdx.x >> 5;
    const int lane = threadIdx.x & 31;
    const int row0 = (blockIdx.x * 8 + warp) * 2;

    unsigned u[2][17];
    unsigned pm[2];
    int      cnt[2];
    float lsum = 0.0f;

    #pragma unroll
    for (int r = 0; r < 2; r++) {
        const float* lg = g_LOG + (size_t)(row0 + r) * NPAD;
        const float* yr = Y + (size_t)(row0 + r) * NC;
        unsigned m = 0;
        #pragma unroll
        for (int i = 0; i < 17; i++) {
            int c = lane + 32 * i;        // max 543 < NPAD: logits in-bounds
            bool v = (c < NC);
            float z  = lg[c];
            float yy = v ? yr[c] : 0.0f;
            float p  = v ? pw[c] : 0.0f;
            float e  = __expf(-fabsf(z));
            float sp = fmaxf(z, 0.0f) + __logf(1.0f + e);   // softplus(z)
            float w  = 1.0f + yy * (p - 1.0f);
            lsum += v ? (w * sp - p * yy * z) : 0.0f;
            m |= (yy != 0.0f) ? (1u << i) : 0u;
            unsigned bb = __float_as_uint(z);
            unsigned uu = bb ^ (((unsigned)((int)bb >> 31)) | 0x80000000u);
            u[r][i] = v ? uu : 0u;        // 0 sorts below every valid key
        }
        pm[r]  = m;
        cnt[r] = __popc(m);
    }

    {
        int q = cnt[0] | (cnt[1] << 16);
        q = __reduce_add_sync(0xffffffffu, q);
        cnt[0] = q & 0xffff; cnt[1] = q >> 16;
    }
    #pragma unroll
    for (int o = 16; o; o >>= 1) lsum += __shfl_xor_sync(0xffffffffu, lsum, o);

    // 2-bit-per-pass radix select: pre = largest prefix with count(u>=pre)>=k.
    unsigned pre[2] = {0u, 0u};
    int cur[2] = {0x7fffffff, 0x7fffffff};
    int done = 0;
    #pragma unroll 1
    for (int bit = 30; bit >= 0; bit -= 2) {
        const unsigned m1 = 2u << bit;   // 1 << (bit+1)
        const unsigned m0 = 1u << bit;
        int pk[2];
        #pragma unroll
        for (int r = 0; r < 2; r++) {
            const unsigned cH  = pre[r] | m1;        // e = 10
            const unsigned cHB = cH | m0;            // e = 11
            const unsigned cL  = pre[r] | m0;        // e = 01
            int nH = 0, nHB = 0, nL = 0;
            #pragma unroll
            for (int i = 0; i < 17; i++) {
                nH  += (u[r][i] >= cH);
                nHB += (u[r][i] >= cHB);
                nL  += (u[r][i] >= cL);
            }
            pk[r] = nH | (nHB << 10) | (nL << 20);
        }
        pk[0] = __reduce_add_sync(0xffffffffu, pk[0]);
        pk[1] = __reduce_add_sync(0xffffffffu, pk[1]);
        #pragma unroll
        for (int r = 0; r < 2; r++) {
            int nH  = pk[r] & 1023;
            int nHB = (pk[r] >> 10) & 1023;
            int nL  = (pk[r] >> 20) & 1023;
            if (nHB >= cnt[r])      { pre[r] |= m1 | m0; cur[r] = nHB; }
            else if (nH >= cnt[r])  { pre[r] |= m1;      cur[r] = nH; }
            else if (nL >= cnt[r])  { pre[r] |= m0;      cur[r] = nL; }
            done |= (cur[r] == cnt[r]) << r;
        }
        if (done == 3) break;            // both selected sets exactly top-k
    }

    int h0 = 0, h1 = 0;
    #pragma unroll
    for (int i = 0; i < 17; i++) {
        h0 += (((pm[0] >> i) & 1u) && (u[0][i] >= pre[0])) ? 1 : 0;
        h1 += (((pm[1] >> i) & 1u) && (u[1][i] >= pre[1])) ? 1 : 0;
    }
    int hh = h0 | (h1 << 16);
    hh = __reduce_add_sync(0xffffffffu, hh);

    if (lane == 0) {
        float sc = (float)(hh & 0xffff) / (float)cnt[0]
                 + (float)(hh >> 16)    / (float)cnt[1];
        atomicAdd(&out[0], lsum * (1.0f / ((float)NB * (float)NC)));
        atomicAdd(&out[1], sc * (1.0f / (float)NB));
    }
}

// ---------------------------------------------------------------------------
// launch
// ---------------------------------------------------------------------------
extern "C" void kernel_launch(void* const* d_in, const int* in_sizes, int n_in,
                              void* d_out, int out_size) {
    const float *x = nullptr, *y = nullptr, *W = nullptr, *b = nullptr, *pwt = nullptr;
    int n527 = 0;
    for (int i = 0; i < n_in; i++) {
        if      (in_sizes[i] == NB * ND) x = (const float*)d_in[i];
        else if (in_sizes[i] == NB * NC) y = (const float*)d_in[i];
        else if (in_sizes[i] == NC * ND) W = (const float*)d_in[i];
        else if (in_sizes[i] == NC) {
            if (n527 == 0) b = (const float*)d_in[i];
            else           pwt = (const float*)d_in[i];
            n527++;
        }
    }
    float* out = (float*)d_out;

    static int smem_set = 0;
    if (!smem_set) {
        cudaFuncSetAttribute(k_gemm, cudaFuncAttributeMaxDynamicSharedMemorySize, SMEM_DYN);
        smem_set = 1;
    }

    __half *xh, *wh;
    cudaGetSymbolAddress((void**)&xh, g_Xh);
    cudaGetSymbolAddress((void**)&wh, g_Wh);

    k_conv<<<2048, 256>>>(x, W);
    dim3 gg(NPAD / BN, NB / BM);   // (3, 256), x fastest
    k_gemm<<<gg, 256, SMEM_DYN>>>(xh, wh, b, out);
    k_reduce<<<NB / 16, 256>>>(y, pwt, out);
}